// round 17
// baseline (speedup 1.0000x reference)
#include <cuda_runtime.h>
#include <cuda_bf16.h>
#include <cuda_fp16.h>

// RK4 + RBF via tabulated A(x). TMA (cp.async.bulk) double-buffered INPUT
// pipeline + direct STG.128 output (no output staging, no bulk-store sync):
//   - TILE = 1024 elems; in: u 4KB + states 8KB per stage, 2 stages.
//   - smem 28KB/block -> 8 blocks/SM, grid 1024 = single resident wave, 4 iters.
//   - per-iter sync: 1 mbar_wait + 1 __syncthreads (round-16 had 4 sync points).
// Builder + PDL unchanged (proven). Fallback classic-LDG main for odd shapes.

#define K_RBF  32
#define N_INT  1024
#define TILE   1024

__device__ __align__(16) unsigned int gTable[N_INT];

__device__ __forceinline__ float ex2_approx(float x) {
    float r;
    asm("ex2.approx.ftz.f32 %0, %1;" : "=f"(r) : "f"(x));
    return r;
}
__device__ __forceinline__ unsigned int smem_u32(const void* p) {
    unsigned int a;
    asm("{ .reg .u64 t; cvta.to.shared.u64 t, %1; cvt.u32.u64 %0, t; }" : "=r"(a) : "l"(p));
    return a;
}

// ---------------- constants ----------------
#define DT_     0.005f
#define M_INV_  (1.0f / 95.452f)
#define OFFST_  (-3.2902f)
#define G_      (214.9261f + 19.3607f)
#define GM_     (G_ * M_INV_)
#define HD2_    (0.5f * DT_ * DT_)
#define HD2M_   (HD2_ * M_INV_)
#define TCONST_ (DT_ - HD2M_ * G_)
#define LOG2E_  1.4426950408889634f
#define SQRT_LOG2E_ 1.2011224087864498f
#define XMIN_   (-8.0f)
#define XSPAN_  16.0f
#define DX_     (XSPAN_ / (float)N_INT)
#define INV_DX_ ((float)N_INT / XSPAN_)

// ---------------- builder (unchanged) ----------------
__global__ void build_table_kernel(const float* __restrict__ centers,
                                   const float* __restrict__ log_sigmas,
                                   const float* __restrict__ w,
                                   const float* __restrict__ bptr)
{
    int j = blockIdx.x * blockDim.x + threadIdx.x;
    if (j >= N_INT) return;
    float bb = bptr[0];
    float x0 = XMIN_ + (float)j * DX_;
    float x1 = x0 + DX_;
    float S0a = 0.f, S0b = 0.f;
#pragma unroll
    for (int k = 0; k < K_RBF; ++k) {
        float a  = ex2_approx(log_sigmas[k] * LOG2E_) * SQRT_LOG2E_;
        float nb = -centers[k] * a;
        float wk = w[k];
        float q0 = fmaf(x0, a, nb);
        float q1 = fmaf(x1, a, nb);
        S0a = fmaf(wk, ex2_approx(-q0 * q0), S0a);
        S0b = fmaf(wk, ex2_approx(-q1 * q1), S0b);
    }
    float A0 = -(OFFST_ + bb + S0a) * M_INV_;
    float A1 = -(OFFST_ + bb + S0b) * M_INV_;
    unsigned int lo = __half_as_ushort(__float2half(A0));
    unsigned int hi = __half_as_ushort(__float2half(A1 - A0));
    gTable[j] = lo | (hi << 16);
}

// ---------------- shared math ----------------
__device__ __forceinline__ void do_elem(float uu, float x,
                                        const unsigned int* tab,
                                        float& o0, float& o1)
{
    float pos = fminf(fmaxf((x - XMIN_) * INV_DX_, 0.0f), (float)N_INT - 0.01f);
    int   i   = (int)pos;
    float f   = pos - (float)i;
    unsigned int e = tab[i];
    __half2 h = *(__half2*)&e;
    float A  = fmaf(f, __high2float(h), __low2float(h));
    float yd = fmaf(uu, M_INV_, fmaf(x, -GM_, A));
    o0 = fmaf(DT_, x, HD2_ * yd);
    o1 = TCONST_ * yd;
}

// ---------------- TMA helpers ----------------
__device__ __forceinline__ void mbar_init(unsigned int a, unsigned int cnt) {
    asm volatile("mbarrier.init.shared.b64 [%0], %1;" :: "r"(a), "r"(cnt) : "memory");
}
__device__ __forceinline__ void mbar_expect_tx(unsigned int a, unsigned int bytes) {
    asm volatile("mbarrier.arrive.expect_tx.shared.b64 _, [%0], %1;"
                 :: "r"(a), "r"(bytes) : "memory");
}
__device__ __forceinline__ void mbar_wait(unsigned int a, unsigned int parity) {
    asm volatile(
        "{\n\t.reg .pred p;\n\t"
        "WAIT_%=:\n\t"
        "mbarrier.try_wait.parity.acquire.cta.shared::cta.b64 p, [%0], %1, 0x989680;\n\t"
        "@!p bra WAIT_%=;\n\t}"
        :: "r"(a), "r"(parity) : "memory");
}
__device__ __forceinline__ void bulk_g2s(unsigned int sdst, const void* gsrc,
                                         unsigned int bytes, unsigned int mbar) {
    asm volatile("cp.async.bulk.shared::cta.global.mbarrier::complete_tx::bytes "
                 "[%0], [%1], %2, [%3];"
                 :: "r"(sdst), "l"(gsrc), "r"(bytes), "r"(mbar) : "memory");
}

// ---------------- TMA-pipelined main (input staging only, direct STG out) ----------------
__global__ __launch_bounds__(256)
void rk4_rbf_tma(const float* __restrict__ u,
                 const float* __restrict__ states,
                 float4* __restrict__ out4,
                 int ntiles_per_block)
{
    __shared__ __align__(16)  unsigned int tab[N_INT];     // 4 KB
    __shared__ __align__(128) float ubuf[2][TILE];         // 8 KB
    __shared__ __align__(128) float stbuf[2][2 * TILE];    // 16 KB
    __shared__ __align__(8)   unsigned long long mbar_s[2];

    const unsigned int U_BYTES  = TILE * 4;      // 4096
    const unsigned int ST_BYTES = TILE * 8;      // 8192

    int t = threadIdx.x;

#if __CUDA_ARCH__ >= 900
    cudaGridDependencySynchronize();             // builder's gTable writes visible
#endif
    ((uint4*)tab)[t] = ((const uint4*)gTable)[t];

    unsigned int mb[2] = { smem_u32(&mbar_s[0]), smem_u32(&mbar_s[1]) };
    if (t == 0) {
        mbar_init(mb[0], 1);
        mbar_init(mb[1], 1);
    }
    __syncthreads();

    long long tile0 = (long long)blockIdx.x;
    long long tstep = (long long)gridDim.x;

    if (t == 0) {
        asm volatile("fence.proxy.async.shared::cta;" ::: "memory");
        for (int it = 0; it < 2 && it < ntiles_per_block; ++it) {
            long long tile = tile0 + (long long)it * tstep;
            mbar_expect_tx(mb[it], U_BYTES + ST_BYTES);
            bulk_g2s(smem_u32(ubuf[it]),  u + tile * TILE,          U_BYTES,  mb[it]);
            bulk_g2s(smem_u32(stbuf[it]), states + tile * 2 * TILE, ST_BYTES, mb[it]);
        }
    }

    for (int it = 0; it < ntiles_per_block; ++it) {
        int s = it & 1;
        unsigned int parity = (unsigned int)((it >> 1) & 1);
        long long tile = tile0 + (long long)it * tstep;

        mbar_wait(mb[s], parity);                // input tile resident

        // compute 4 elems/thread, direct STG.128 out (fire-and-forget)
        float4 uu = ((const float4*)ubuf[s])[t];
        float4 s0 = ((const float4*)stbuf[s])[2 * t];
        float4 s1 = ((const float4*)stbuf[s])[2 * t + 1];

        float4 o0, o1;
        do_elem(uu.x, s0.y, tab, o0.x, o0.y);
        do_elem(uu.y, s0.w, tab, o0.z, o0.w);
        do_elem(uu.z, s1.y, tab, o1.x, o1.y);
        do_elem(uu.w, s1.w, tab, o1.z, o1.w);

        long long obase = tile * (TILE / 2) + 2 * t;   // float4 index
        out4[obase]     = o0;
        out4[obase + 1] = o1;

        __syncthreads();                          // buffer s fully consumed

        if (t == 0) {
            int it2 = it + 2;
            if (it2 < ntiles_per_block) {
                long long tile2 = tile0 + (long long)it2 * tstep;
                asm volatile("fence.proxy.async.shared::cta;" ::: "memory");
                mbar_expect_tx(mb[s], U_BYTES + ST_BYTES);
                bulk_g2s(smem_u32(ubuf[s]),  u + tile2 * TILE,          U_BYTES,  mb[s]);
                bulk_g2s(smem_u32(stbuf[s]), states + tile2 * 2 * TILE, ST_BYTES, mb[s]);
            }
        }
    }
}

// ---------------- fallback classic main (round-15 proven) ----------------
__global__ __launch_bounds__(256)
void rk4_rbf_main(const float4* __restrict__ u4,
                  const float4* __restrict__ st4,
                  float4* __restrict__ out4,
                  int nquads)
{
    __shared__ unsigned int tab[N_INT];
    int t = threadIdx.x;
#if __CUDA_ARCH__ >= 900
    cudaGridDependencySynchronize();
#endif
    ((uint4*)tab)[t] = ((const uint4*)gTable)[t];
    __syncthreads();

    int stride = gridDim.x * blockDim.x;
    for (int p = blockIdx.x * blockDim.x + t; p < nquads; p += stride) {
        float4 uu = u4[p];
        float4 s0 = st4[2 * p];
        float4 s1 = st4[2 * p + 1];
        float4 o0, o1;
        do_elem(uu.x, s0.y, tab, o0.x, o0.y);
        do_elem(uu.y, s0.w, tab, o0.z, o0.w);
        do_elem(uu.z, s1.y, tab, o1.x, o1.y);
        do_elem(uu.w, s1.w, tab, o1.z, o1.w);
        out4[2 * p]     = o0;
        out4[2 * p + 1] = o1;
    }
}

extern "C" void kernel_launch(void* const* d_in, const int* in_sizes, int n_in,
                              void* d_out, int out_size) {
    const float* u        = (const float*)d_in[0];
    const float* states   = (const float*)d_in[1];
    const float* centers  = (const float*)d_in[2];
    const float* lsig     = (const float*)d_in[3];
    const float* w        = (const float*)d_in[4];
    const float* b        = (const float*)d_in[5];

    int n = in_sizes[0];                 // 4194304
    const int BLOCKS = 1024, THREADS = 256;

    build_table_kernel<<<(N_INT + 255) / 256, 256>>>(centers, lsig, w, b);

    cudaLaunchConfig_t cfg = {};
    cfg.gridDim  = dim3(BLOCKS, 1, 1);
    cfg.blockDim = dim3(THREADS, 1, 1);
    cfg.dynamicSmemBytes = 0;
    cfg.stream = 0;
    cudaLaunchAttribute attr[1];
    attr[0].id = cudaLaunchAttributeProgrammaticStreamSerialization;
    attr[0].val.programmaticStreamSerializationAllowed = 1;
    cfg.attrs = attr;
    cfg.numAttrs = 1;

    if (n % (TILE * BLOCKS) == 0) {
        int ntiles_per_block = n / (TILE * BLOCKS);     // 4 for n=4194304
        cudaError_t e = cudaLaunchKernelEx(&cfg, rk4_rbf_tma,
                                           u, states, (float4*)d_out, ntiles_per_block);
        if (e != cudaSuccess) {
            (void)cudaGetLastError();
            rk4_rbf_tma<<<BLOCKS, THREADS>>>(u, states, (float4*)d_out, ntiles_per_block);
        }
    } else {
        int nquads = n / 4;
        cudaError_t e = cudaLaunchKernelEx(&cfg, rk4_rbf_main,
                                           (const float4*)u, (const float4*)states,
                                           (float4*)d_out, nquads);
        if (e != cudaSuccess) {
            (void)cudaGetLastError();
            rk4_rbf_main<<<BLOCKS, THREADS>>>((const float4*)u, (const float4*)states,
                                              (float4*)d_out, nquads);
        }
    }
}